// round 8
// baseline (speedup 1.0000x reference)
#include <cuda_runtime.h>
#include <cstdint>

#define N_NODES 50000
#define D 128
#define MAXDEG 96
#define SPAD 132   // padded row stride for transposed W in smem

// ---- per-launch scratch (device globals) ----
__device__ int  g_cnt[N_NODES];
__device__ int2 g_bkt[N_NODES * MAXDEG];   // {src, __float_as_int(e)} per dst

// ---------------------------------------------------------------------------
// Bucket append, 2 edges per thread (maximizes resident threads for atomic
// latency hiding; fill is latency-bound, not throughput-bound).
// ---------------------------------------------------------------------------
__global__ void fill_buckets_kernel(const int* __restrict__ esrc,
                                    const int* __restrict__ edst,
                                    const float* __restrict__ ee, int E) {
    int i = blockIdx.x * blockDim.x + threadIdx.x;
    int base = i * 2;
    if (base + 1 < E) {
        int2   s2 = *reinterpret_cast<const int2*>(esrc + base);
        int2   d2 = *reinterpret_cast<const int2*>(edst + base);
        float2 e2 = *reinterpret_cast<const float2*>(ee + base);
        int p0 = atomicAdd(&g_cnt[d2.x], 1);
        int p1 = atomicAdd(&g_cnt[d2.y], 1);
        if (p0 < MAXDEG) g_bkt[d2.x * MAXDEG + p0] = make_int2(s2.x, __float_as_int(e2.x));
        if (p1 < MAXDEG) g_bkt[d2.y * MAXDEG + p1] = make_int2(s2.y, __float_as_int(e2.y));
    } else if (base < E) {
        int d = edst[base];
        int p = atomicAdd(&g_cnt[d], 1);
        if (p < MAXDEG) g_bkt[d * MAXDEG + p] = make_int2(esrc[base], __float_as_int(ee[base]));
    }
}

// ---------------------------------------------------------------------------
// Packed fp32 helpers (Blackwell f32x2 pipe; ptxas won't auto-generate these)
// ---------------------------------------------------------------------------
__device__ __forceinline__ unsigned long long fma2(unsigned long long a,
                                                   unsigned long long b,
                                                   unsigned long long c) {
    unsigned long long d;
    asm("fma.rn.f32x2 %0, %1, %2, %3;" : "=l"(d) : "l"(a), "l"(b), "l"(c));
    return d;
}
__device__ __forceinline__ unsigned long long pack2(float lo, float hi) {
    unsigned long long d;
    asm("mov.b64 %0, {%1, %2};" : "=l"(d) : "f"(lo), "f"(hi));
    return d;
}
__device__ __forceinline__ float2 unpack2(unsigned long long v) {
    float lo, hi;
    asm("mov.b64 {%0, %1}, %2;" : "=f"(lo), "=f"(hi) : "l"(v));
    return make_float2(lo, hi);
}

// ---------------------------------------------------------------------------
// Fused kernel: prefetched bucket stages + 2-node interleaved gather (MLP 16)
// + f4-broadcast packed-fp32 matvec (4-node blocking) + epilogue.
// out[n] = relu((W @ S[n] + b*c[n]) / max(deg[n],1)) + alpha[n]*feat[n]
// ---------------------------------------------------------------------------
__global__ void __launch_bounds__(256, 2) fused_kernel(
    const float* __restrict__ feat, const float* __restrict__ alpha,
    const float* __restrict__ W, const float* __restrict__ b,
    float* __restrict__ out) {
    extern __shared__ float smx[];
    float* Ws = smx;                 // [D][SPAD]  Ws[k*SPAD + i] = W[i][k]
    float* Ss = smx + D * SPAD;      // [8 warps][4 nodes][D]

    int tid = threadIdx.x, warp = tid >> 5, lane = tid & 31;

    for (int idx = tid; idx < D * D; idx += blockDim.x) {
        int i = idx >> 7;            // output dim
        int k = idx & (D - 1);       // input dim
        Ws[k * SPAD + i] = W[idx];   // 4-way-conflict STS (one-time)
    }
    __syncthreads();

    const int oi = lane * 4;
    float4 bb = *reinterpret_cast<const float4*>(b + oi);
    float* ss = Ss + warp * (4 * D);
    const float4* feat4 = reinterpret_cast<const float4*>(feat);
    const unsigned fullm = 0xffffffffu;

    const int NPT = 32;              // 8 warps * 4 nodes per block-tile
    const int numTiles = (N_NODES + NPT - 1) / NPT;
    for (int tile = blockIdx.x; tile < numTiles; tile += gridDim.x) {
        int n0 = tile * NPT + warp * 4;

        // ---- prefetch: cnt + first-32 bucket stage for all 4 nodes ----
        int nn[4], craw[4], cnts[4];
        int2 pr[4];
        #pragma unroll
        for (int r = 0; r < 4; r++) { int n = n0 + r; nn[r] = (n < N_NODES) ? n : 0; }
        #pragma unroll
        for (int r = 0; r < 4; r++) craw[r] = g_cnt[nn[r]];
        #pragma unroll
        for (int r = 0; r < 4; r++)
            pr[r] = g_bkt[(size_t)nn[r] * MAXDEG + lane];   // lane<32<MAXDEG: always in-bounds
        int   sv_[4]; float ev_[4];
        #pragma unroll
        for (int r = 0; r < 4; r++) {
            cnts[r] = ((n0 + r) < N_NODES) ? min(craw[r], MAXDEG) : 0;
            bool ok = lane < cnts[r];
            sv_[r] = ok ? pr[r].x : 0;
            ev_[r] = ok ? __int_as_float(pr[r].y) : 0.f;
        }

        // ---- gather: two nodes interleaved per pass (MLP 16) ----
        float cs[4];
        #pragma unroll
        for (int p = 0; p < 2; p++) {
            int r0 = 2 * p, r1 = r0 + 1;
            float4 a0 = make_float4(0.f, 0.f, 0.f, 0.f);
            float4 a1 = make_float4(0.f, 0.f, 0.f, 0.f);
            float c0 = 0.f, c1 = 0.f;
            int m0 = min(cnts[r0], 32), m1 = min(cnts[r1], 32);
            #pragma unroll
            for (int j8 = 0; j8 < 32; j8 += 8) {
                bool d0 = j8 < m0, d1 = j8 < m1;
                float4 v0[8], v1[8];
                if (d0) {
                    #pragma unroll
                    for (int t = 0; t < 8; t++) {
                        int s = __shfl_sync(fullm, sv_[r0], j8 + t);
                        v0[t] = feat4[(size_t)s * 32 + lane];
                    }
                }
                if (d1) {
                    #pragma unroll
                    for (int t = 0; t < 8; t++) {
                        int s = __shfl_sync(fullm, sv_[r1], j8 + t);
                        v1[t] = feat4[(size_t)s * 32 + lane];
                    }
                }
                if (d0) {
                    #pragma unroll
                    for (int t = 0; t < 8; t++) {
                        float e = __shfl_sync(fullm, ev_[r0], j8 + t);
                        a0.x += e * v0[t].x; a0.y += e * v0[t].y;
                        a0.z += e * v0[t].z; a0.w += e * v0[t].w;
                        c0 += e;
                    }
                }
                if (d1) {
                    #pragma unroll
                    for (int t = 0; t < 8; t++) {
                        float e = __shfl_sync(fullm, ev_[r1], j8 + t);
                        a1.x += e * v1[t].x; a1.y += e * v1[t].y;
                        a1.z += e * v1[t].z; a1.w += e * v1[t].w;
                        c1 += e;
                    }
                }
            }
            // rare tail: deg > 32
            #pragma unroll
            for (int q = 0; q < 2; q++) {
                int r = r0 + q;
                if (cnts[r] > 32) {
                    const int2* bp = g_bkt + (size_t)nn[r] * MAXDEG;
                    for (int bas = 32; bas < cnts[r]; bas += 32) {
                        int idx = bas + lane;
                        int2 q2 = (idx < cnts[r]) ? bp[idx] : make_int2(0, 0);
                        int   sl = q2.x;
                        float el = (idx < cnts[r]) ? __int_as_float(q2.y) : 0.f;
                        int m = min(cnts[r] - bas, 32);
                        for (int j = 0; j < m; j += 8) {
                            #pragma unroll
                            for (int t = 0; t < 8; t++) {
                                int   s = __shfl_sync(fullm, sl, j + t);
                                float e = __shfl_sync(fullm, el, j + t);
                                float4 v = feat4[(size_t)s * 32 + lane];
                                if (q == 0) {
                                    a0.x += e * v.x; a0.y += e * v.y;
                                    a0.z += e * v.z; a0.w += e * v.w;
                                    c0 += e;
                                } else {
                                    a1.x += e * v.x; a1.y += e * v.y;
                                    a1.z += e * v.z; a1.w += e * v.w;
                                    c1 += e;
                                }
                            }
                        }
                    }
                }
            }
            reinterpret_cast<float4*>(ss + r0 * D)[lane] = a0;
            reinterpret_cast<float4*>(ss + r1 * D)[lane] = a1;
            cs[r0] = c0; cs[r1] = c1;
        }
        __syncwarp();

        // ---- matvec: f4-broadcast S reads, packed f32x2 FMA ----
        unsigned long long acc2[4][2];
        #pragma unroll
        for (int r = 0; r < 4; r++) { acc2[r][0] = 0ull; acc2[r][1] = 0ull; }

        for (int k4 = 0; k4 < D / 4; k4++) {
            unsigned long long wp[4][2];
            #pragma unroll
            for (int t = 0; t < 4; t++) {
                float4 w = *reinterpret_cast<const float4*>(&Ws[(k4 * 4 + t) * SPAD + oi]);
                wp[t][0] = pack2(w.x, w.y);
                wp[t][1] = pack2(w.z, w.w);
            }
            #pragma unroll
            for (int r = 0; r < 4; r++) {
                float4 sv = *reinterpret_cast<const float4*>(&ss[r * D + k4 * 4]);
                unsigned long long s0 = pack2(sv.x, sv.x);
                unsigned long long s1 = pack2(sv.y, sv.y);
                unsigned long long s2 = pack2(sv.z, sv.z);
                unsigned long long s3 = pack2(sv.w, sv.w);
                acc2[r][0] = fma2(wp[0][0], s0, acc2[r][0]);
                acc2[r][1] = fma2(wp[0][1], s0, acc2[r][1]);
                acc2[r][0] = fma2(wp[1][0], s1, acc2[r][0]);
                acc2[r][1] = fma2(wp[1][1], s1, acc2[r][1]);
                acc2[r][0] = fma2(wp[2][0], s2, acc2[r][0]);
                acc2[r][1] = fma2(wp[2][1], s2, acc2[r][1]);
                acc2[r][0] = fma2(wp[3][0], s3, acc2[r][0]);
                acc2[r][1] = fma2(wp[3][1], s3, acc2[r][1]);
            }
        }

        #pragma unroll
        for (int r = 0; r < 4; r++) {
            int n = n0 + r;
            if (n < N_NODES) {
                float2 a01 = unpack2(acc2[r][0]);
                float2 a23 = unpack2(acc2[r][1]);
                float cv = cs[r];
                float inv = 1.0f / fmaxf((float)cnts[r], 1.0f);
                float av = alpha[n];
                float4 f = feat4[(size_t)n * 32 + lane];
                float4 o;
                o.x = fmaxf((a01.x + bb.x * cv) * inv, 0.f) + av * f.x;
                o.y = fmaxf((a01.y + bb.y * cv) * inv, 0.f) + av * f.y;
                o.z = fmaxf((a23.x + bb.z * cv) * inv, 0.f) + av * f.z;
                o.w = fmaxf((a23.y + bb.w * cv) * inv, 0.f) + av * f.w;
                reinterpret_cast<float4*>(out + (size_t)n * D)[lane] = o;
            }
        }
        __syncwarp();
    }
}

extern "C" void kernel_launch(void* const* d_in, const int* in_sizes, int n_in,
                              void* d_out, int out_size) {
    const float* feat  = (const float*)d_in[0];
    const float* alpha = (const float*)d_in[1];
    const int*   esrc  = (const int*)d_in[2];
    const int*   edst  = (const int*)d_in[3];
    const float* ee    = (const float*)d_in[4];
    const float* W     = (const float*)d_in[5];
    const float* b     = (const float*)d_in[6];
    float* out = (float*)d_out;
    const int E = in_sizes[2];

    void* cnt_ptr = nullptr;
    cudaGetSymbolAddress(&cnt_ptr, g_cnt);
    cudaMemsetAsync(cnt_ptr, 0, N_NODES * sizeof(int));

    int fill_threads = (E + 1) / 2;
    fill_buckets_kernel<<<(fill_threads + 255) / 256, 256>>>(esrc, edst, ee, E);

    const int smem_bytes = (D * SPAD + 8 * 4 * D) * (int)sizeof(float);  // 83968 B
    cudaFuncSetAttribute(fused_kernel,
                         cudaFuncAttributeMaxDynamicSharedMemorySize, smem_bytes);
    fused_kernel<<<296, 256, smem_bytes>>>(feat, alpha, W, b, out);
}

// round 9
// speedup vs baseline: 1.1558x; 1.1558x over previous
#include <cuda_runtime.h>
#include <cstdint>

#define N_NODES 50000
#define D 128
#define MAXDEG 96
#define SPAD 132   // padded row stride for transposed W in smem

// ---- per-launch scratch (device globals) ----
__device__ int  g_cnt[N_NODES];
__device__ int2 g_bkt[N_NODES * MAXDEG];   // {src, __float_as_int(e)} per dst

// ---------------------------------------------------------------------------
// Bucket append, 4 edges per thread (vectorized loads, batched atomics).
// ---------------------------------------------------------------------------
__global__ void fill_buckets_kernel(const int* __restrict__ esrc,
                                    const int* __restrict__ edst,
                                    const float* __restrict__ ee, int E) {
    int i = blockIdx.x * blockDim.x + threadIdx.x;
    int base = i * 4;
    if (base + 3 < E) {
        int4   s4 = *reinterpret_cast<const int4*>(esrc + base);
        int4   d4 = *reinterpret_cast<const int4*>(edst + base);
        float4 e4 = *reinterpret_cast<const float4*>(ee + base);
        int p0 = atomicAdd(&g_cnt[d4.x], 1);
        int p1 = atomicAdd(&g_cnt[d4.y], 1);
        int p2 = atomicAdd(&g_cnt[d4.z], 1);
        int p3 = atomicAdd(&g_cnt[d4.w], 1);
        if (p0 < MAXDEG) g_bkt[d4.x * MAXDEG + p0] = make_int2(s4.x, __float_as_int(e4.x));
        if (p1 < MAXDEG) g_bkt[d4.y * MAXDEG + p1] = make_int2(s4.y, __float_as_int(e4.y));
        if (p2 < MAXDEG) g_bkt[d4.z * MAXDEG + p2] = make_int2(s4.z, __float_as_int(e4.z));
        if (p3 < MAXDEG) g_bkt[d4.w * MAXDEG + p3] = make_int2(s4.w, __float_as_int(e4.w));
    } else {
        for (int k = base; k < E; k++) {
            int d = edst[k];
            int p = atomicAdd(&g_cnt[d], 1);
            if (p < MAXDEG) g_bkt[d * MAXDEG + p] = make_int2(esrc[k], __float_as_int(ee[k]));
        }
    }
}

// ---------------------------------------------------------------------------
// Packed fp32 helpers (Blackwell f32x2 pipe; ptxas won't auto-generate these)
// ---------------------------------------------------------------------------
__device__ __forceinline__ unsigned long long fma2(unsigned long long a,
                                                   unsigned long long b,
                                                   unsigned long long c) {
    unsigned long long d;
    asm("fma.rn.f32x2 %0, %1, %2, %3;" : "=l"(d) : "l"(a), "l"(b), "l"(c));
    return d;
}
__device__ __forceinline__ unsigned long long pack2(float lo, float hi) {
    unsigned long long d;
    asm("mov.b64 %0, {%1, %2};" : "=l"(d) : "f"(lo), "f"(hi));
    return d;
}
__device__ __forceinline__ float2 unpack2(unsigned long long v) {
    float lo, hi;
    asm("mov.b64 {%0, %1}, %2;" : "=f"(lo), "=f"(hi) : "l"(v));
    return make_float2(lo, hi);
}

// ---------------------------------------------------------------------------
// Fused (R3 structure, 85-reg budget): per-node bucket gather (warp-staged +
// SHFL, MLP 8) + packed-fp32 matvec (4-node blocking, scalar-broadcast S).
// out[n] = relu((W @ S[n] + b*c[n]) / max(deg[n],1)) + alpha[n]*feat[n]
// ---------------------------------------------------------------------------
__global__ void __launch_bounds__(256, 2) fused_kernel(
    const float* __restrict__ feat, const float* __restrict__ alpha,
    const float* __restrict__ W, const float* __restrict__ b,
    float* __restrict__ out) {
    extern __shared__ float smx[];
    float* Ws = smx;               // [D][SPAD]  Ws[k*SPAD + i] = W[i][k]
    float* Ss = smx + D * SPAD;    // [8 warps][4 nodes][D]

    int tid = threadIdx.x, warp = tid >> 5, lane = tid & 31;

    for (int idx = tid; idx < D * D; idx += blockDim.x) {
        int i = idx >> 7;          // output dim
        int k = idx & (D - 1);     // input dim
        Ws[k * SPAD + i] = W[idx];
    }
    __syncthreads();

    const int oi = lane * 4;
    float4 bb = *reinterpret_cast<const float4*>(b + oi);
    float* ss = Ss + warp * (4 * D);
    const float4* feat4 = reinterpret_cast<const float4*>(feat);

    const int numTiles = (N_NODES + 31) / 32;
    for (int tile = blockIdx.x; tile < numTiles; tile += gridDim.x) {
        int n0 = tile * 32 + warp * 4;

        float cs[4], degs[4];
        #pragma unroll
        for (int r = 0; r < 4; r++) {
            int n = n0 + r;
            float4 a = make_float4(0.f, 0.f, 0.f, 0.f);
            float c = 0.f;
            int cnt = 0;
            if (n < N_NODES) {
                cnt = min(g_cnt[n], MAXDEG);
                const int2* bp = g_bkt + (size_t)n * MAXDEG;
                for (int base = 0; base < cnt; base += 32) {
                    // lane index always < MAXDEG: load unconditionally, mask e.
                    int2 pr = bp[base + lane];
                    int   sl = pr.x;
                    float el = (base + lane < cnt) ? __int_as_float(pr.y) : 0.f;
                    int m = min(cnt - base, 32);
                    for (int j = 0; j < m; j += 8) {
                        int   s8[8]; float e8[8];
                        #pragma unroll
                        for (int t = 0; t < 8; t++) {
                            s8[t] = __shfl_sync(0xffffffffu, sl, j + t);
                            e8[t] = __shfl_sync(0xffffffffu, el, j + t);
                        }
                        float4 v[8];
                        #pragma unroll
                        for (int t = 0; t < 8; t++)
                            v[t] = feat4[(size_t)s8[t] * 32 + lane];
                        #pragma unroll
                        for (int t = 0; t < 8; t++) {
                            a.x += e8[t] * v[t].x;
                            a.y += e8[t] * v[t].y;
                            a.z += e8[t] * v[t].z;
                            a.w += e8[t] * v[t].w;
                            c += e8[t];
                        }
                    }
                }
            }
            reinterpret_cast<float4*>(ss + r * D)[lane] = a;
            cs[r] = c;
            degs[r] = (float)cnt;
        }
        __syncwarp();

        unsigned long long acc2[4][2];
        #pragma unroll
        for (int r = 0; r < 4; r++) { acc2[r][0] = 0ull; acc2[r][1] = 0ull; }

        #pragma unroll 4
        for (int k = 0; k < D; k++) {
            float4 w = *reinterpret_cast<const float4*>(&Ws[k * SPAD + oi]);
            unsigned long long wxy = pack2(w.x, w.y);
            unsigned long long wzw = pack2(w.z, w.w);
            #pragma unroll
            for (int r = 0; r < 4; r++) {
                float sv = ss[r * D + k];                 // broadcast LDS
                unsigned long long sv2 = pack2(sv, sv);
                acc2[r][0] = fma2(wxy, sv2, acc2[r][0]);
                acc2[r][1] = fma2(wzw, sv2, acc2[r][1]);
            }
        }

        #pragma unroll
        for (int r = 0; r < 4; r++) {
            int n = n0 + r;
            if (n < N_NODES) {
                float2 a01 = unpack2(acc2[r][0]);
                float2 a23 = unpack2(acc2[r][1]);
                float cv = cs[r];
                float inv = 1.0f / fmaxf(degs[r], 1.0f);
                float av = alpha[n];
                float4 f = feat4[(size_t)n * 32 + lane];
                float4 o;
                o.x = fmaxf((a01.x + bb.x * cv) * inv, 0.f) + av * f.x;
                o.y = fmaxf((a01.y + bb.y * cv) * inv, 0.f) + av * f.y;
                o.z = fmaxf((a23.x + bb.z * cv) * inv, 0.f) + av * f.z;
                o.w = fmaxf((a23.y + bb.w * cv) * inv, 0.f) + av * f.w;
                reinterpret_cast<float4*>(out + (size_t)n * D)[lane] = o;
            }
        }
        __syncwarp();
    }
}

extern "C" void kernel_launch(void* const* d_in, const int* in_sizes, int n_in,
                              void* d_out, int out_size) {
    const float* feat  = (const float*)d_in[0];
    const float* alpha = (const float*)d_in[1];
    const int*   esrc  = (const int*)d_in[2];
    const int*   edst  = (const int*)d_in[3];
    const float* ee    = (const float*)d_in[4];
    const float* W     = (const float*)d_in[5];
    const float* b     = (const float*)d_in[6];
    float* out = (float*)d_out;
    const int E = in_sizes[2];

    void* cnt_ptr = nullptr;
    cudaGetSymbolAddress(&cnt_ptr, g_cnt);
    cudaMemsetAsync(cnt_ptr, 0, N_NODES * sizeof(int));

    int fill_threads = (E + 3) / 4;
    fill_buckets_kernel<<<(fill_threads + 255) / 256, 256>>>(esrc, edst, ee, E);

    const int smem_bytes = (D * SPAD + 8 * 4 * D) * (int)sizeof(float);  // 83968 B
    cudaFuncSetAttribute(fused_kernel,
                         cudaFuncAttributeMaxDynamicSharedMemorySize, smem_bytes);
    fused_kernel<<<296, 256, smem_bytes>>>(feat, alpha, W, b, out);
}